// round 12
// baseline (speedup 1.0000x reference)
#include <cuda_runtime.h>
#include <cuda_fp16.h>
#include <cstdint>

#define NG 3
#define PP 8
#define BB 8
#define CCH 128
#define SSQ 1024
#define LLQ 64
#define HH 4
#define DH 32
#define SCALE_F 0.17677669529663687f

// Scratch (static __device__ arrays: allocation-free per harness rules)
__device__ __align__(256) __half g_xh [BB*SSQ*CCH];     // [b][s][c]  fp16
__device__ __align__(256) __half g_wkh[NG*CCH*CCH];     // [g][i][c]  fp16
__device__ __align__(256) __half g_wvh[NG*CCH*CCH];     // [g][i][c]  fp16
__device__ __align__(256) __half g_kh[NG*BB*SSQ*CCH];   // [g][b][s][c]  fp16
__device__ __align__(256) __half g_vh[NG*BB*CCH*SSQ];   // [g][b][c][s]  fp16
__device__ __align__(256) float  g_q [NG*PP*LLQ*CCH];   // [g][p][l][i]  fp32
__device__ __align__(256) float  g_heat[NG*BB*PP*SSQ];  // [g][b][p][s]
__device__ float g_dist[NG*BB*PP];                      // [g][b][p]
__device__ int   g_cnt [NG*BB*PP];                      // finalize tickets

__device__ __forceinline__ void mma16816(float& c0, float& c1, float& c2, float& c3,
                                         uint32_t a0, uint32_t a1, uint32_t a2, uint32_t a3,
                                         uint32_t b0, uint32_t b1) {
    asm volatile("mma.sync.aligned.m16n8k16.row.col.f32.f16.f16.f32 "
                 "{%0,%1,%2,%3},{%4,%5,%6,%7},{%8,%9},{%0,%1,%2,%3};"
                 : "+f"(c0), "+f"(c1), "+f"(c2), "+f"(c3)
                 : "r"(a0), "r"(a1), "r"(a2), "r"(a3), "r"(b0), "r"(b1));
}
__device__ __forceinline__ uint32_t ldh2(const __half* p) {
    return *reinterpret_cast<const uint32_t*>(p);
}
__device__ __forceinline__ uint32_t packh2(float a, float b) {
    __half2 h = __floats2half2_rn(a, b);
    return reinterpret_cast<uint32_t&>(h);
}

// ---------------------------------------------------------------------------
// Fused prologue: one launch, three independent jobs branched on blockIdx.x.
//   CTAs [0,768)    : zero heat/dist/cnt + convert weights to fp16
//   CTAs [768,1024) : x [b][c][s] fp32 -> g_xh [b][s][c] fp16 (64x64 transpose)
//   CTAs [1024,1120): q projection (fp32), single-sync full-smem GEMM
#define PQ_PS   0
#define PQ_WS   (64*132)
#define FP_TOT  ((64*132 + 32*132) * 4)

__global__ void __launch_bounds__(256, 2) fused_pre_kernel(
        const float* __restrict__ x,     const float* __restrict__ proto,
        const float* __restrict__ qw,    const float* __restrict__ kw,
        const float* __restrict__ vw) {
    extern __shared__ float smq[];
    int bid = blockIdx.x;
    int tid = threadIdx.x;

    if (bid < 768) {
        // ---------------- prep ----------------
        int i = bid * 256 + tid;                 // 0..196607
        g_heat[i] = 0.f;                          // exactly NG*BB*PP*SSQ
        if (i < NG*BB*PP) { g_dist[i] = 0.f; g_cnt[i] = 0; }
        if (i < NG*CCH*CCH) {
            g_wkh[i] = __float2half(kw[i]);
            g_wvh[i] = __float2half(vw[i]);
        }
        return;
    }
    if (bid < 1024) {
        // ---------------- convert_x ----------------
        int cb = bid - 768;                      // 0..255
        int s0 = (cb & 15) * 64;
        int c0 = ((cb >> 4) & 1) * 64;
        int b  = cb >> 5;
        float* Ts = smq;                         // [64][68]
        const float* xb = x + ((size_t)b * CCH + c0) * SSQ + s0;
        #pragma unroll
        for (int r = 0; r < 4; r++) {
            int id = tid + 256 * r;              // 0..1023 float4 units
            int cc = id >> 4, f4 = id & 15;
            float4 v = *(const float4*)(xb + (size_t)cc * SSQ + f4 * 4);
            *(float4*)&Ts[cc * 68 + f4 * 4] = v;
        }
        __syncthreads();
        __half* xo = g_xh + ((size_t)b * SSQ + s0) * CCH + c0;
        #pragma unroll
        for (int r = 0; r < 8; r++) {
            int id = tid + 256 * r;              // 0..2047 half2 units
            int ss = id >> 5, cp = id & 31;
            __half2 h = __floats2half2_rn(Ts[(cp*2) * 68 + ss], Ts[(cp*2+1) * 68 + ss]);
            *(__half2*)(xo + (size_t)ss * CCH + cp * 2) = h;
        }
        return;
    }
    // ---------------- proj_q ----------------
    {
        int qb = bid - 1024;                     // 0..95
        int gp = qb % 24;
        int i0 = (qb / 24) * 32;
        int g  = gp >> 3;
        float* Ps = smq + PQ_PS;                 // [64][132]  (l-major)
        float* Ws = smq + PQ_WS;                 // [32][132]
        const float* pg  = proto + (size_t)gp * CCH * LLQ;
        const float* qwg = qw + (size_t)g * CCH * CCH;

        #pragma unroll
        for (int r = 0; r < 32; r++) {
            int id = tid + 256 * r;              // 0..8191
            int c = id >> 6, l = id & 63;
            Ps[l * 132 + c] = pg[id];
        }
        #pragma unroll
        for (int r = 0; r < 4; r++) {
            int id4 = tid + 256 * r;             // 0..1023
            int row = id4 >> 5, c4 = id4 & 31;
            float4 v = *(const float4*)(qwg + (size_t)(i0 + row) * CCH + c4 * 4);
            *(float4*)&Ws[row * 132 + c4 * 4] = v;
        }
        __syncthreads();

        int tx = tid & 15, ty = tid >> 4;
        float acc[4][2] = {};
        #pragma unroll
        for (int c4 = 0; c4 < 32; c4++) {
            float4 wv0 = *(const float4*)&Ws[tx * 132 + c4 * 4];
            float4 wv1 = *(const float4*)&Ws[(tx + 16) * 132 + c4 * 4];
            #pragma unroll
            for (int a = 0; a < 4; a++) {
                float4 pv = *(const float4*)&Ps[(ty + 16*a) * 132 + c4 * 4];
                acc[a][0] += pv.x*wv0.x + pv.y*wv0.y + pv.z*wv0.z + pv.w*wv0.w;
                acc[a][1] += pv.x*wv1.x + pv.y*wv1.y + pv.z*wv1.z + pv.w*wv1.w;
            }
        }
        float* qo = g_q + (size_t)gp * LLQ * CCH;
        #pragma unroll
        for (int a = 0; a < 4; a++) {
            qo[(ty + 16*a) * CCH + i0 + tx]      = acc[a][0];
            qo[(ty + 16*a) * CCH + i0 + tx + 16] = acc[a][1];
        }
    }
}

// ---------------------------------------------------------------------------
// K/V projection via fp16 mma: out K[s][i], V[i][s] per (g,b).
#define PJ_XS   0
#define PJ_WK   34816
#define PJ_WV   52224
#define PJ_ST   69632
#define PJ_TOT  88064

__global__ void __launch_bounds__(256, 2) proj_kv_mma_kernel() {
    extern __shared__ char smraw[];
    __half* Xs = (__half*)(smraw + PJ_XS);   // [128][136]
    __half* Wk = (__half*)(smraw + PJ_WK);   // [64][136]
    __half* Wv = (__half*)(smraw + PJ_WV);   // [64][136]
    __half* St = (__half*)(smraw + PJ_ST);

    int s0 = blockIdx.x * 128, i1 = blockIdx.y * 64;
    int gb = blockIdx.z;
    int g = gb >> 3, b = gb & 7;
    int tid = threadIdx.x, lane = tid & 31, w = tid >> 5;
    int gr = lane >> 2, tc = lane & 3;
    int mt = w & 3, nh = w >> 2;

    {
        const __half* src = g_xh + ((size_t)b * SSQ + s0) * CCH;
        #pragma unroll
        for (int r = 0; r < 8; r++) {
            int id = tid + 256 * r;          // 0..2047
            int row = id >> 4, q = id & 15;
            *(uint4*)(Xs + row * 136 + q * 8) =
                *(const uint4*)(src + (size_t)row * CCH + q * 8);
        }
        const __half* sk = g_wkh + (size_t)(g * CCH + i1) * CCH;
        const __half* sv = g_wvh + (size_t)(g * CCH + i1) * CCH;
        #pragma unroll
        for (int r = 0; r < 4; r++) {
            int id = tid + 256 * r;          // 0..1023
            int row = id >> 4, q = id & 15;
            *(uint4*)(Wk + row * 136 + q * 8) = *(const uint4*)(sk + (size_t)row * CCH + q * 8);
            *(uint4*)(Wv + row * 136 + q * 8) = *(const uint4*)(sv + (size_t)row * CCH + q * 8);
        }
    }
    __syncthreads();

    // ---- K = Wk @ X^T ----
    float cK[8][4] = {};
    {
        const __half* A = Wk + (mt * 16) * 136;
        #pragma unroll
        for (int kk = 0; kk < 8; kk++) {
            uint32_t a0 = ldh2(A + gr * 136 + kk*16 + tc*2);
            uint32_t a1 = ldh2(A + (gr+8) * 136 + kk*16 + tc*2);
            uint32_t a2 = ldh2(A + gr * 136 + kk*16 + tc*2 + 8);
            uint32_t a3 = ldh2(A + (gr+8) * 136 + kk*16 + tc*2 + 8);
            #pragma unroll
            for (int nt = 0; nt < 8; nt++) {
                const __half* Bp = Xs + (nh*64 + nt*8 + gr) * 136 + kk*16 + tc*2;
                uint32_t b0 = ldh2(Bp), b1 = ldh2(Bp + 8);
                mma16816(cK[nt][0], cK[nt][1], cK[nt][2], cK[nt][3],
                         a0, a1, a2, a3, b0, b1);
            }
        }
    }
    #pragma unroll
    for (int nt = 0; nt < 8; nt++) {
        int sl = nh*64 + nt*8 + tc*2;
        int il = mt*16 + gr;
        St[sl * 72 + il]       = __float2half(cK[nt][0]);
        St[(sl+1) * 72 + il]   = __float2half(cK[nt][1]);
        St[sl * 72 + il + 8]   = __float2half(cK[nt][2]);
        St[(sl+1) * 72 + il+8] = __float2half(cK[nt][3]);
    }
    __syncthreads();
    {
        __half* kout = g_kh + (size_t)gb * SSQ * CCH;
        #pragma unroll
        for (int r = 0; r < 4; r++) {
            int id = tid + 256 * r;          // 0..1023
            int row = id >> 3, q = id & 7;
            *(uint4*)(kout + (size_t)(s0 + row) * CCH + i1 + q * 8) =
                *(const uint4*)(St + row * 72 + q * 8);
        }
    }

    // ---- V = Wv @ X^T ----
    float cV[8][4] = {};
    {
        const __half* A = Wv + (mt * 16) * 136;
        #pragma unroll
        for (int kk = 0; kk < 8; kk++) {
            uint32_t a0 = ldh2(A + gr * 136 + kk*16 + tc*2);
            uint32_t a1 = ldh2(A + (gr+8) * 136 + kk*16 + tc*2);
            uint32_t a2 = ldh2(A + gr * 136 + kk*16 + tc*2 + 8);
            uint32_t a3 = ldh2(A + (gr+8) * 136 + kk*16 + tc*2 + 8);
            #pragma unroll
            for (int nt = 0; nt < 8; nt++) {
                const __half* Bp = Xs + (nh*64 + nt*8 + gr) * 136 + kk*16 + tc*2;
                uint32_t b0 = ldh2(Bp), b1 = ldh2(Bp + 8);
                mma16816(cV[nt][0], cV[nt][1], cV[nt][2], cV[nt][3],
                         a0, a1, a2, a3, b0, b1);
            }
        }
    }
    __syncthreads();
    #pragma unroll
    for (int nt = 0; nt < 8; nt++) {
        int sl = nh*64 + nt*8 + tc*2;
        int il = mt*16 + gr;
        *(__half2*)(St + il * 136 + sl)       = __floats2half2_rn(cV[nt][0], cV[nt][1]);
        *(__half2*)(St + (il+8) * 136 + sl)   = __floats2half2_rn(cV[nt][2], cV[nt][3]);
    }
    __syncthreads();
    {
        __half* vout = g_vh + (size_t)gb * CCH * SSQ;
        #pragma unroll
        for (int r = 0; r < 4; r++) {
            int id = tid + 256 * r;          // 0..1023
            int row = id >> 4, q = id & 15;
            *(uint4*)(vout + (size_t)(i1 + row) * SSQ + s0 + q * 8) =
                *(const uint4*)(St + row * 136 + q * 8);
        }
    }
}

// ---------------------------------------------------------------------------
// Fused flash attention + in-kernel finalize (threadfence-reduction).
// One CTA per (g,b,h,p,lc); the 8th CTA to finish a (g,b,p) does its argmax.
#define AT_K     0
#define AT_V     20480
#define AT_E     42240
#define AT_OUT   108288
#define AT_ZS    112512
#define AT_IZ    112640
#define AT_RED   112768
#define AT_TOT   112800
#define KBUF_H   5120     // K buffer stride (halfs) = 128*40
#define VBUF_H   5440     // V buffer stride (halfs) = 40*136
#define EST      1032
#define KST      40
#define VST      136

__global__ void __launch_bounds__(256, 2) attn_kernel(float* __restrict__ out,
                                                      int out_size) {
    extern __shared__ char smraw[];
    __half* Kb   = (__half*)(smraw + AT_K);
    __half* Vb   = (__half*)(smraw + AT_V);
    __half* E    = (__half*)(smraw + AT_E);
    float* out_sf= (float*)(smraw + AT_OUT);   // [32][33]
    float* zsh   = (float*)(smraw + AT_ZS);
    float* iz    = (float*)(smraw + AT_IZ);
    float* red   = (float*)(smraw + AT_RED);
    __shared__ int winflag;

    int idx = blockIdx.x;                  // 1536 = g(3) b(8) h(4) p(8) lc(2)
    int lc = idx & 1, p = (idx >> 1) & 7, h = (idx >> 4) & 3,
        b = (idx >> 6) & 7, g = idx >> 9;
    int tid = threadIdx.x, lane = tid & 31, w = tid >> 5;
    int gr = lane >> 2, tc = lane & 3;
    int lbase = lc * 32;
    int gbp = (g*BB + b) * PP + p;

    const __half* Kg = g_kh + (size_t)(g*BB + b) * SSQ * CCH + h * DH;   // [s][128]+off
    const __half* Vg = g_vh + ((size_t)((g*BB + b) * CCH) + h * DH) * SSQ;
    const float*  Qg = g_q  + (size_t)(g*PP + p) * LLQ * CCH;

    int mh = w >> 2;                       // row half: rows mh*16..+16
    int ng = w & 3;                        // s-block of 32 within 128-s tile
    int plid = mh * 32 + lane;             // pair-local index 0..63
    int r_lo = mh * 16 + gr, r_hi = r_lo + 8;

    // zero reduction buffers
    #pragma unroll
    for (int r = 0; r < 5; r++) {
        int id = tid + 256 * r;
        if (id < 1056) out_sf[id] = 0.f;
    }
    if (tid < 32) zsh[tid] = 0.f;
    // init V extra rows (32 = ones, 33..39 = zeros) in BOTH buffers
    for (int id = tid; id < 2 * 8 * VST; id += 256) {
        int buf = id / (8 * VST);
        int rem = id - buf * 8 * VST;
        int rrow = rem / VST, cc = rem % VST;
        Vb[buf * VBUF_H + (32 + rrow) * VST + cc] =
            (rrow == 0) ? __float2half(1.f) : __float2half(0.f);
    }

    // A fragments for QK from global q (fp32 -> half2)
    uint32_t aq[2][4];
    {
        const float* q0 = Qg + (size_t)(lbase + r_lo) * CCH + h * DH;
        const float* q1 = q0 + 8 * CCH;
        #pragma unroll
        for (int ks = 0; ks < 2; ks++) {
            float2 f0 = *(const float2*)(q0 + ks*16 + tc*2);
            float2 f1 = *(const float2*)(q1 + ks*16 + tc*2);
            float2 f2 = *(const float2*)(q0 + ks*16 + tc*2 + 8);
            float2 f3 = *(const float2*)(q1 + ks*16 + tc*2 + 8);
            aq[ks][0] = packh2(f0.x, f0.y);
            aq[ks][1] = packh2(f1.x, f1.y);
            aq[ks][2] = packh2(f2.x, f2.y);
            aq[ks][3] = packh2(f3.x, f3.y);
        }
    }

    // Per-pair slice loads: pair ng loads K rows [ng*32,+32) and V cols [ng*32,+32).
    auto loadK = [&](int st, int bf) {
        const __half* src = Kg + (size_t)st * 128 * CCH;
        __half* dst = Kb + bf * KBUF_H;
        #pragma unroll
        for (int it = 0; it < 2; it++) {
            int id = plid + 64 * it;       // 0..127
            int rl = ng*32 + (id >> 2), ch = id & 3;
            *(uint4*)(dst + rl * KST + ch * 8) =
                *(const uint4*)(src + (size_t)rl * CCH + ch * 8);
        }
    };
    auto loadV = [&](int st, int bf) {
        const __half* src = Vg + st * 128 + ng * 32;
        __half* dst = Vb + bf * VBUF_H + ng * 32;
        #pragma unroll
        for (int it = 0; it < 2; it++) {
            int id = plid + 64 * it;       // 0..127
            int d = id >> 2, ch = id & 3;
            *(uint4*)(dst + d * VST + ch * 8) =
                *(const uint4*)(src + (size_t)d * SSQ + ch * 8);
        }
    };

    loadK(0, 0);
    loadV(0, 0);
    __syncthreads();                       // init (ones rows etc.) + prologue visible

    float pv[5][4] = {};                   // nd 0..3: out tiles; nd 4: Z (ones row)

    for (int st = 0; st < 8; st++) {
        if (st > 0)
            asm volatile("bar.sync %0, 64;" :: "r"(ng + 1) : "memory");
        if (st < 7) { loadK(st + 1, (st + 1) & 1); loadV(st + 1, (st + 1) & 1); }
        const __half* Kt = Kb + (st & 1) * KBUF_H;
        const __half* Vt = Vb + (st & 1) * VBUF_H;

        // ---- QK: 4 independent C-tiles (16 mmas, 4-deep chains) ----
        float c[4][4] = {};
        #pragma unroll
        for (int nt = 0; nt < 4; nt++) {
            const __half* kb = Kt + (ng*32 + nt*8 + gr) * KST;
            #pragma unroll
            for (int ks = 0; ks < 2; ks++) {
                uint32_t b0 = ldh2(kb + ks*16 + tc*2);
                uint32_t b1 = ldh2(kb + ks*16 + tc*2 + 8);
                mma16816(c[nt][0], c[nt][1], c[nt][2], c[nt][3],
                         aq[ks][0], aq[ks][1], aq[ks][2], aq[ks][3], b0, b1);
            }
        }
        // ---- exp + pack + E store ----
        uint32_t af[4][2];
        #pragma unroll
        for (int nt = 0; nt < 4; nt++) {
            float e0 = __expf(c[nt][0] * SCALE_F), e1 = __expf(c[nt][1] * SCALE_F);
            float e2 = __expf(c[nt][2] * SCALE_F), e3 = __expf(c[nt][3] * SCALE_F);
            af[nt][0] = packh2(e0, e1);
            af[nt][1] = packh2(e2, e3);
            int scol = st*128 + ng*32 + nt*8 + tc*2;
            *(uint32_t*)&E[r_lo * EST + scol] = af[nt][0];
            *(uint32_t*)&E[r_hi * EST + scol] = af[nt][1];
        }
        // ---- PV + Z: nd 0..3 = out, nd 4 hits the ones row (d=32) ----
        #pragma unroll
        for (int j = 0; j < 2; j++) {
            int sloc = ng*32 + j*16 + tc*2;
            #pragma unroll
            for (int nd = 0; nd < 5; nd++) {
                const __half* vbp = Vt + (nd*8 + gr) * VST + sloc;
                uint32_t b0 = ldh2(vbp);
                uint32_t b1 = ldh2(vbp + 8);
                mma16816(pv[nd][0], pv[nd][1], pv[nd][2], pv[nd][3],
                         af[2*j][0], af[2*j][1], af[2*j+1][0], af[2*j+1][1], b0, b1);
            }
        }
    }

    // ---- Z: pv[4][0]/[2] at tc==0 hold row sums over this warp's s-slice ----
    if (tc == 0) {
        atomicAdd(&zsh[r_lo], pv[4][0]);
        atomicAdd(&zsh[r_hi], pv[4][2]);
    }
    // ---- out partial reduction across ng-warps ----
    #pragma unroll
    for (int nd = 0; nd < 4; nd++) {
        int d = nd*8 + tc*2;
        atomicAdd(&out_sf[r_lo*33 + d],     pv[nd][0]);
        atomicAdd(&out_sf[r_lo*33 + d + 1], pv[nd][1]);
        atomicAdd(&out_sf[r_hi*33 + d],     pv[nd][2]);
        atomicAdd(&out_sf[r_hi*33 + d + 1], pv[nd][3]);
    }
    __syncthreads();                       // E complete + zsh/out atomics done
    if (tid < 32) iz[tid] = 1.f / zsh[tid];
    __syncthreads();

    // ---- heat (uint2 loads: 4 s-columns per thread) ----
    float* hout = g_heat + (size_t)gbp * SSQ;
    {
        int scol = tid * 4;
        float hs0 = 0.f, hs1 = 0.f, hs2 = 0.f, hs3 = 0.f;
        #pragma unroll
        for (int r = 0; r < 32; r++) {
            uint2 u = *(const uint2*)&E[r * EST + scol];
            float2 fa = __half22float2(reinterpret_cast<__half2&>(u.x));
            float2 fb = __half22float2(reinterpret_cast<__half2&>(u.y));
            float izr = iz[r];
            hs0 += fa.x * izr; hs1 += fa.y * izr;
            hs2 += fb.x * izr; hs3 += fb.y * izr;
        }
        atomicAdd(&hout[scol],     hs0);
        atomicAdd(&hout[scol + 1], hs1);
        atomicAdd(&hout[scol + 2], hs2);
        atomicAdd(&hout[scol + 3], hs3);
    }

    // ---- dist ----
    float dacc = 0.f;
    #pragma unroll
    for (int r = 0; r < 4; r++) {
        int id = tid + 256 * r;            // 0..1023
        int row = id >> 5, d = id & 31;
        float o = out_sf[row*33 + d] * iz[row];
        float qv = Qg[(size_t)(lbase + row) * CCH + h * DH + d];
        float e = qv - o;
        dacc += e * e;
    }
    #pragma unroll
    for (int o = 16; o; o >>= 1) dacc += __shfl_xor_sync(0xffffffffu, dacc, o);
    if (lane == 0) red[w] = dacc;
    __syncthreads();
    if (w == 0) {
        float v = (lane < 8) ? red[lane] : 0.f;
        #pragma unroll
        for (int o = 4; o; o >>= 1) v += __shfl_xor_sync(0xffffffffu, v, o);
        if (lane == 0) atomicAdd(&g_dist[gbp], v);
    }

    // ---- fused finalize: last of 8 CTAs for this gbp does the argmax ----
    __threadfence();                       // make this CTA's atomics visible
    __syncthreads();                       // all threads fenced
    if (tid == 0) {
        int old = atomicAdd(&g_cnt[gbp], 1);
        winflag = (old == 7);
    }
    __syncthreads();
    if (winflag) {
        float* bv  = (float*)(smraw + AT_E);         // reuse dead E region
        int*   bix = (int*)(smraw + AT_E + 1024);
        float4 hv = *(const float4*)&hout[tid * 4];
        float best = hv.x; int bi = tid * 4;
        if (hv.y > best) { best = hv.y; bi = tid*4 + 1; }
        if (hv.z > best) { best = hv.z; bi = tid*4 + 2; }
        if (hv.w > best) { best = hv.w; bi = tid*4 + 3; }
        bv[tid] = best; bix[tid] = bi;
        __syncthreads();
        for (int s2 = 128; s2; s2 >>= 1) {
            if (tid < s2) {
                if (bv[tid + s2] > bv[tid] ||
                    (bv[tid + s2] == bv[tid] && bix[tid + s2] < bix[tid])) {
                    bv[tid] = bv[tid + s2]; bix[tid] = bix[tid + s2];
                }
            }
            __syncthreads();
        }
        if (tid == 0) {
            int col = g * PP + p;
            out[b * 24 + col] = g_dist[gbp] * (1.f / (64.f * 128.f));
            if (out_size >= 384)
                out[192 + b * 24 + col] = (float)bix[0];
        }
    }
}

// ---------------------------------------------------------------------------
extern "C" void kernel_launch(void* const* d_in, const int* in_sizes, int n_in,
                              void* d_out, int out_size) {
    const float* x     = (const float*)d_in[0];
    const float* proto = (const float*)d_in[1];
    const float* qw    = (const float*)d_in[2];
    const float* kw    = (const float*)d_in[3];
    const float* vw    = (const float*)d_in[4];
    float* out = (float*)d_out;

    cudaFuncSetAttribute(attn_kernel,
                         cudaFuncAttributeMaxDynamicSharedMemorySize, AT_TOT);
    cudaFuncSetAttribute(proj_kv_mma_kernel,
                         cudaFuncAttributeMaxDynamicSharedMemorySize, PJ_TOT);
    cudaFuncSetAttribute(fused_pre_kernel,
                         cudaFuncAttributeMaxDynamicSharedMemorySize, FP_TOT);

    fused_pre_kernel<<<1120, 256, FP_TOT>>>(x, proto, qw, kw, vw);
    proj_kv_mma_kernel<<<dim3(8, 2, 24), 256, PJ_TOT>>>();
    attn_kernel<<<1536, 256, AT_TOT>>>(out, out_size);
}

// round 13
// speedup vs baseline: 1.0527x; 1.0527x over previous
#include <cuda_runtime.h>
#include <cuda_fp16.h>
#include <cstdint>

#define NG 3
#define PP 8
#define BB 8
#define CCH 128
#define SSQ 1024
#define LLQ 64
#define HH 4
#define DH 32
#define SCALE_F 0.17677669529663687f

// Scratch (static __device__ arrays: allocation-free per harness rules)
__device__ __align__(256) __half g_xh [BB*SSQ*CCH];     // [b][s][c]  fp16
__device__ __align__(256) __half g_wkh[NG*CCH*CCH];     // [g][i][c]  fp16
__device__ __align__(256) __half g_wvh[NG*CCH*CCH];     // [g][i][c]  fp16
__device__ __align__(256) __half g_kh[NG*BB*SSQ*CCH];   // [g][b][s][c]  fp16
__device__ __align__(256) __half g_vh[NG*BB*CCH*SSQ];   // [g][b][c][s]  fp16
__device__ __align__(256) float  g_q [NG*PP*LLQ*CCH];   // [g][p][l][i]  fp32
__device__ __align__(256) float  g_heat[NG*BB*PP*SSQ];  // [g][b][p][s]
__device__ float g_dist[NG*BB*PP];                      // [g][b][p]

__device__ __forceinline__ void mma16816(float& c0, float& c1, float& c2, float& c3,
                                         uint32_t a0, uint32_t a1, uint32_t a2, uint32_t a3,
                                         uint32_t b0, uint32_t b1) {
    asm volatile("mma.sync.aligned.m16n8k16.row.col.f32.f16.f16.f32 "
                 "{%0,%1,%2,%3},{%4,%5,%6,%7},{%8,%9},{%0,%1,%2,%3};"
                 : "+f"(c0), "+f"(c1), "+f"(c2), "+f"(c3)
                 : "r"(a0), "r"(a1), "r"(a2), "r"(a3), "r"(b0), "r"(b1));
}
__device__ __forceinline__ uint32_t ldh2(const __half* p) {
    return *reinterpret_cast<const uint32_t*>(p);
}
__device__ __forceinline__ uint32_t packh2(float a, float b) {
    __half2 h = __floats2half2_rn(a, b);
    return reinterpret_cast<uint32_t&>(h);
}

// ---------------------------------------------------------------------------
// Fused prologue: one launch, three independent jobs branched on blockIdx.x.
#define PQ_PS   0
#define PQ_WS   (64*132)
#define FP_TOT  ((64*132 + 32*132) * 4)

__global__ void __launch_bounds__(256, 2) fused_pre_kernel(
        const float* __restrict__ x,     const float* __restrict__ proto,
        const float* __restrict__ qw,    const float* __restrict__ kw,
        const float* __restrict__ vw) {
    extern __shared__ float smq[];
    int bid = blockIdx.x;
    int tid = threadIdx.x;

    if (bid < 768) {
        // ---------------- prep ----------------
        int i = bid * 256 + tid;                 // 0..196607
        g_heat[i] = 0.f;                          // exactly NG*BB*PP*SSQ
        if (i < NG*BB*PP) g_dist[i] = 0.f;
        if (i < NG*CCH*CCH) {
            g_wkh[i] = __float2half(kw[i]);
            g_wvh[i] = __float2half(vw[i]);
        }
        return;
    }
    if (bid < 1024) {
        // ---------------- convert_x ----------------
        int cb = bid - 768;                      // 0..255
        int s0 = (cb & 15) * 64;
        int c0 = ((cb >> 4) & 1) * 64;
        int b  = cb >> 5;
        float* Ts = smq;                         // [64][68]
        const float* xb = x + ((size_t)b * CCH + c0) * SSQ + s0;
        #pragma unroll
        for (int r = 0; r < 4; r++) {
            int id = tid + 256 * r;              // 0..1023 float4 units
            int cc = id >> 4, f4 = id & 15;
            float4 v = *(const float4*)(xb + (size_t)cc * SSQ + f4 * 4);
            *(float4*)&Ts[cc * 68 + f4 * 4] = v;
        }
        __syncthreads();
        __half* xo = g_xh + ((size_t)b * SSQ + s0) * CCH + c0;
        #pragma unroll
        for (int r = 0; r < 8; r++) {
            int id = tid + 256 * r;              // 0..2047 half2 units
            int ss = id >> 5, cp = id & 31;
            __half2 h = __floats2half2_rn(Ts[(cp*2) * 68 + ss], Ts[(cp*2+1) * 68 + ss]);
            *(__half2*)(xo + (size_t)ss * CCH + cp * 2) = h;
        }
        return;
    }
    // ---------------- proj_q ----------------
    {
        int qb = bid - 1024;                     // 0..95
        int gp = qb % 24;
        int i0 = (qb / 24) * 32;
        int g  = gp >> 3;
        float* Ps = smq + PQ_PS;                 // [64][132]  (l-major)
        float* Ws = smq + PQ_WS;                 // [32][132]
        const float* pg  = proto + (size_t)gp * CCH * LLQ;
        const float* qwg = qw + (size_t)g * CCH * CCH;

        #pragma unroll
        for (int r = 0; r < 32; r++) {
            int id = tid + 256 * r;              // 0..8191
            int c = id >> 6, l = id & 63;
            Ps[l * 132 + c] = pg[id];
        }
        #pragma unroll
        for (int r = 0; r < 4; r++) {
            int id4 = tid + 256 * r;             // 0..1023
            int row = id4 >> 5, c4 = id4 & 31;
            float4 v = *(const float4*)(qwg + (size_t)(i0 + row) * CCH + c4 * 4);
            *(float4*)&Ws[row * 132 + c4 * 4] = v;
        }
        __syncthreads();

        int tx = tid & 15, ty = tid >> 4;
        float acc[4][2] = {};
        #pragma unroll
        for (int c4 = 0; c4 < 32; c4++) {
            float4 wv0 = *(const float4*)&Ws[tx * 132 + c4 * 4];
            float4 wv1 = *(const float4*)&Ws[(tx + 16) * 132 + c4 * 4];
            #pragma unroll
            for (int a = 0; a < 4; a++) {
                float4 pv = *(const float4*)&Ps[(ty + 16*a) * 132 + c4 * 4];
                acc[a][0] += pv.x*wv0.x + pv.y*wv0.y + pv.z*wv0.z + pv.w*wv0.w;
                acc[a][1] += pv.x*wv1.x + pv.y*wv1.y + pv.z*wv1.z + pv.w*wv1.w;
            }
        }
        float* qo = g_q + (size_t)gp * LLQ * CCH;
        #pragma unroll
        for (int a = 0; a < 4; a++) {
            qo[(ty + 16*a) * CCH + i0 + tx]      = acc[a][0];
            qo[(ty + 16*a) * CCH + i0 + tx + 16] = acc[a][1];
        }
    }
}

// ---------------------------------------------------------------------------
// K/V projection via fp16 mma: out K[s][i], V[i][s] per (g,b).
#define PJ_XS   0
#define PJ_WK   34816
#define PJ_WV   52224
#define PJ_ST   69632
#define PJ_TOT  88064

__global__ void __launch_bounds__(256, 2) proj_kv_mma_kernel() {
    extern __shared__ char smraw[];
    __half* Xs = (__half*)(smraw + PJ_XS);   // [128][136]
    __half* Wk = (__half*)(smraw + PJ_WK);   // [64][136]
    __half* Wv = (__half*)(smraw + PJ_WV);   // [64][136]
    __half* St = (__half*)(smraw + PJ_ST);

    int s0 = blockIdx.x * 128, i1 = blockIdx.y * 64;
    int gb = blockIdx.z;
    int g = gb >> 3, b = gb & 7;
    int tid = threadIdx.x, lane = tid & 31, w = tid >> 5;
    int gr = lane >> 2, tc = lane & 3;
    int mt = w & 3, nh = w >> 2;

    {
        const __half* src = g_xh + ((size_t)b * SSQ + s0) * CCH;
        #pragma unroll
        for (int r = 0; r < 8; r++) {
            int id = tid + 256 * r;          // 0..2047
            int row = id >> 4, q = id & 15;
            *(uint4*)(Xs + row * 136 + q * 8) =
                *(const uint4*)(src + (size_t)row * CCH + q * 8);
        }
        const __half* sk = g_wkh + (size_t)(g * CCH + i1) * CCH;
        const __half* sv = g_wvh + (size_t)(g * CCH + i1) * CCH;
        #pragma unroll
        for (int r = 0; r < 4; r++) {
            int id = tid + 256 * r;          // 0..1023
            int row = id >> 4, q = id & 15;
            *(uint4*)(Wk + row * 136 + q * 8) = *(const uint4*)(sk + (size_t)row * CCH + q * 8);
            *(uint4*)(Wv + row * 136 + q * 8) = *(const uint4*)(sv + (size_t)row * CCH + q * 8);
        }
    }
    __syncthreads();

    // ---- K = Wk @ X^T ----
    float cK[8][4] = {};
    {
        const __half* A = Wk + (mt * 16) * 136;
        #pragma unroll
        for (int kk = 0; kk < 8; kk++) {
            uint32_t a0 = ldh2(A + gr * 136 + kk*16 + tc*2);
            uint32_t a1 = ldh2(A + (gr+8) * 136 + kk*16 + tc*2);
            uint32_t a2 = ldh2(A + gr * 136 + kk*16 + tc*2 + 8);
            uint32_t a3 = ldh2(A + (gr+8) * 136 + kk*16 + tc*2 + 8);
            #pragma unroll
            for (int nt = 0; nt < 8; nt++) {
                const __half* Bp = Xs + (nh*64 + nt*8 + gr) * 136 + kk*16 + tc*2;
                uint32_t b0 = ldh2(Bp), b1 = ldh2(Bp + 8);
                mma16816(cK[nt][0], cK[nt][1], cK[nt][2], cK[nt][3],
                         a0, a1, a2, a3, b0, b1);
            }
        }
    }
    #pragma unroll
    for (int nt = 0; nt < 8; nt++) {
        int sl = nh*64 + nt*8 + tc*2;
        int il = mt*16 + gr;
        St[sl * 72 + il]       = __float2half(cK[nt][0]);
        St[(sl+1) * 72 + il]   = __float2half(cK[nt][1]);
        St[sl * 72 + il + 8]   = __float2half(cK[nt][2]);
        St[(sl+1) * 72 + il+8] = __float2half(cK[nt][3]);
    }
    __syncthreads();
    {
        __half* kout = g_kh + (size_t)gb * SSQ * CCH;
        #pragma unroll
        for (int r = 0; r < 4; r++) {
            int id = tid + 256 * r;          // 0..1023
            int row = id >> 3, q = id & 7;
            *(uint4*)(kout + (size_t)(s0 + row) * CCH + i1 + q * 8) =
                *(const uint4*)(St + row * 72 + q * 8);
        }
    }

    // ---- V = Wv @ X^T ----
    float cV[8][4] = {};
    {
        const __half* A = Wv + (mt * 16) * 136;
        #pragma unroll
        for (int kk = 0; kk < 8; kk++) {
            uint32_t a0 = ldh2(A + gr * 136 + kk*16 + tc*2);
            uint32_t a1 = ldh2(A + (gr+8) * 136 + kk*16 + tc*2);
            uint32_t a2 = ldh2(A + gr * 136 + kk*16 + tc*2 + 8);
            uint32_t a3 = ldh2(A + (gr+8) * 136 + kk*16 + tc*2 + 8);
            #pragma unroll
            for (int nt = 0; nt < 8; nt++) {
                const __half* Bp = Xs + (nh*64 + nt*8 + gr) * 136 + kk*16 + tc*2;
                uint32_t b0 = ldh2(Bp), b1 = ldh2(Bp + 8);
                mma16816(cV[nt][0], cV[nt][1], cV[nt][2], cV[nt][3],
                         a0, a1, a2, a3, b0, b1);
            }
        }
    }
    __syncthreads();
    #pragma unroll
    for (int nt = 0; nt < 8; nt++) {
        int sl = nh*64 + nt*8 + tc*2;
        int il = mt*16 + gr;
        *(__half2*)(St + il * 136 + sl)       = __floats2half2_rn(cV[nt][0], cV[nt][1]);
        *(__half2*)(St + (il+8) * 136 + sl)   = __floats2half2_rn(cV[nt][2], cV[nt][3]);
    }
    __syncthreads();
    {
        __half* vout = g_vh + (size_t)gb * CCH * SSQ;
        #pragma unroll
        for (int r = 0; r < 4; r++) {
            int id = tid + 256 * r;          // 0..1023
            int row = id >> 4, q = id & 15;
            *(uint4*)(vout + (size_t)(i1 + row) * SSQ + s0 + q * 8) =
                *(const uint4*)(St + row * 136 + q * 8);
        }
    }
}

// ---------------------------------------------------------------------------
// Fused flash attention (round-11 structure: no fence/ticket).
#define AT_K     0
#define AT_V     20480
#define AT_E     42240
#define AT_OUT   108288
#define AT_ZS    112512
#define AT_IZ    112640
#define AT_RED   112768
#define AT_TOT   112800
#define KBUF_H   5120     // K buffer stride (halfs) = 128*40
#define VBUF_H   5440     // V buffer stride (halfs) = 40*136
#define EST      1032
#define KST      40
#define VST      136

__global__ void __launch_bounds__(256, 2) attn_kernel() {
    extern __shared__ char smraw[];
    __half* Kb   = (__half*)(smraw + AT_K);
    __half* Vb   = (__half*)(smraw + AT_V);
    __half* E    = (__half*)(smraw + AT_E);
    float* out_sf= (float*)(smraw + AT_OUT);   // [32][33]
    float* zsh   = (float*)(smraw + AT_ZS);
    float* iz    = (float*)(smraw + AT_IZ);
    float* red   = (float*)(smraw + AT_RED);

    int idx = blockIdx.x;                  // 1536 = g(3) b(8) h(4) p(8) lc(2)
    int lc = idx & 1, p = (idx >> 1) & 7, h = (idx >> 4) & 3,
        b = (idx >> 6) & 7, g = idx >> 9;
    int tid = threadIdx.x, lane = tid & 31, w = tid >> 5;
    int gr = lane >> 2, tc = lane & 3;
    int lbase = lc * 32;
    int gbp = (g*BB + b) * PP + p;

    const __half* Kg = g_kh + (size_t)(g*BB + b) * SSQ * CCH + h * DH;   // [s][128]+off
    const __half* Vg = g_vh + ((size_t)((g*BB + b) * CCH) + h * DH) * SSQ;
    const float*  Qg = g_q  + (size_t)(g*PP + p) * LLQ * CCH;

    int mh = w >> 2;                       // row half: rows mh*16..+16
    int ng = w & 3;                        // s-block of 32 within 128-s tile
    int plid = mh * 32 + lane;             // pair-local index 0..63
    int r_lo = mh * 16 + gr, r_hi = r_lo + 8;

    // zero reduction buffers
    #pragma unroll
    for (int r = 0; r < 5; r++) {
        int id = tid + 256 * r;
        if (id < 1056) out_sf[id] = 0.f;
    }
    if (tid < 32) zsh[tid] = 0.f;
    // init V extra rows (32 = ones, 33..39 = zeros) in BOTH buffers
    for (int id = tid; id < 2 * 8 * VST; id += 256) {
        int buf = id / (8 * VST);
        int rem = id - buf * 8 * VST;
        int rrow = rem / VST, cc = rem % VST;
        Vb[buf * VBUF_H + (32 + rrow) * VST + cc] =
            (rrow == 0) ? __float2half(1.f) : __float2half(0.f);
    }

    // A fragments for QK from global q (fp32 -> half2)
    uint32_t aq[2][4];
    {
        const float* q0 = Qg + (size_t)(lbase + r_lo) * CCH + h * DH;
        const float* q1 = q0 + 8 * CCH;
        #pragma unroll
        for (int ks = 0; ks < 2; ks++) {
            float2 f0 = *(const float2*)(q0 + ks*16 + tc*2);
            float2 f1 = *(const float2*)(q1 + ks*16 + tc*2);
            float2 f2 = *(const float2*)(q0 + ks*16 + tc*2 + 8);
            float2 f3 = *(const float2*)(q1 + ks*16 + tc*2 + 8);
            aq[ks][0] = packh2(f0.x, f0.y);
            aq[ks][1] = packh2(f1.x, f1.y);
            aq[ks][2] = packh2(f2.x, f2.y);
            aq[ks][3] = packh2(f3.x, f3.y);
        }
    }

    // Per-pair slice loads: pair ng loads K rows [ng*32,+32) and V cols [ng*32,+32).
    auto loadK = [&](int st, int bf) {
        const __half* src = Kg + (size_t)st * 128 * CCH;
        __half* dst = Kb + bf * KBUF_H;
        #pragma unroll
        for (int it = 0; it < 2; it++) {
            int id = plid + 64 * it;       // 0..127
            int rl = ng*32 + (id >> 2), ch = id & 3;
            *(uint4*)(dst + rl * KST + ch * 8) =
                *(const uint4*)(src + (size_t)rl * CCH + ch * 8);
        }
    };
    auto loadV = [&](int st, int bf) {
        const __half* src = Vg + st * 128 + ng * 32;
        __half* dst = Vb + bf * VBUF_H + ng * 32;
        #pragma unroll
        for (int it = 0; it < 2; it++) {
            int id = plid + 64 * it;       // 0..127
            int d = id >> 2, ch = id & 3;
            *(uint4*)(dst + d * VST + ch * 8) =
                *(const uint4*)(src + (size_t)d * SSQ + ch * 8);
        }
    };

    loadK(0, 0);
    loadV(0, 0);
    __syncthreads();                       // init (ones rows etc.) + prologue visible

    float pv[5][4] = {};                   // nd 0..3: out tiles; nd 4: Z (ones row)

    for (int st = 0; st < 8; st++) {
        if (st > 0)
            asm volatile("bar.sync %0, 64;" :: "r"(ng + 1) : "memory");
        if (st < 7) { loadK(st + 1, (st + 1) & 1); loadV(st + 1, (st + 1) & 1); }
        const __half* Kt = Kb + (st & 1) * KBUF_H;
        const __half* Vt = Vb + (st & 1) * VBUF_H;

        // ---- QK: 4 independent C-tiles (16 mmas, 4-deep chains) ----
        float c[4][4] = {};
        #pragma unroll
        for (int nt = 0; nt < 4; nt++) {
            const __half* kb = Kt + (ng*32 + nt*8 + gr) * KST;
            #pragma unroll
            for (int ks = 0; ks < 2; ks++) {
                uint32_t b0 = ldh2(kb + ks*16 + tc*2);
                uint32_t b1 = ldh2(kb + ks*16 + tc*2 + 8);
                mma16816(c[nt][0], c[nt][1], c[nt][2], c[nt][3],
                         aq[ks][0], aq[ks][1], aq[ks][2], aq[ks][3], b0, b1);
            }
        }
        // ---- exp + pack + E store ----
        uint32_t af[4][2];
        #pragma unroll
        for (int nt = 0; nt < 4; nt++) {
            float e0 = __expf(c[nt][0] * SCALE_F), e1 = __expf(c[nt][1] * SCALE_F);
            float e2 = __expf(c[nt][2] * SCALE_F), e3 = __expf(c[nt][3] * SCALE_F);
            af[nt][0] = packh2(e0, e1);
            af[nt][1] = packh2(e2, e3);
            int scol = st*128 + ng*32 + nt*8 + tc*2;
            *(uint32_t*)&E[r_lo * EST + scol] = af[nt][0];
            *(uint32_t*)&E[r_hi * EST + scol] = af[nt][1];
        }
        // ---- PV + Z: nd 0..3 = out, nd 4 hits the ones row (d=32) ----
        #pragma unroll
        for (int j = 0; j < 2; j++) {
            int sloc = ng*32 + j*16 + tc*2;
            #pragma unroll
            for (int nd = 0; nd < 5; nd++) {
                const __half* vbp = Vt + (nd*8 + gr) * VST + sloc;
                uint32_t b0 = ldh2(vbp);
                uint32_t b1 = ldh2(vbp + 8);
                mma16816(pv[nd][0], pv[nd][1], pv[nd][2], pv[nd][3],
                         af[2*j][0], af[2*j][1], af[2*j+1][0], af[2*j+1][1], b0, b1);
            }
        }
    }

    // ---- Z: pv[4][0]/[2] at tc==0 hold row sums over this warp's s-slice ----
    if (tc == 0) {
        atomicAdd(&zsh[r_lo], pv[4][0]);
        atomicAdd(&zsh[r_hi], pv[4][2]);
    }
    // ---- out partial reduction across ng-warps ----
    #pragma unroll
    for (int nd = 0; nd < 4; nd++) {
        int d = nd*8 + tc*2;
        atomicAdd(&out_sf[r_lo*33 + d],     pv[nd][0]);
        atomicAdd(&out_sf[r_lo*33 + d + 1], pv[nd][1]);
        atomicAdd(&out_sf[r_hi*33 + d],     pv[nd][2]);
        atomicAdd(&out_sf[r_hi*33 + d + 1], pv[nd][3]);
    }
    __syncthreads();                       // E complete + zsh/out atomics done
    if (tid < 32) iz[tid] = 1.f / zsh[tid];
    __syncthreads();

    // ---- heat (uint2 loads: 4 s-columns per thread) ----
    float* hout = g_heat + (size_t)gbp * SSQ;
    {
        int scol = tid * 4;
        float hs0 = 0.f, hs1 = 0.f, hs2 = 0.f, hs3 = 0.f;
        #pragma unroll
        for (int r = 0; r < 32; r++) {
            uint2 u = *(const uint2*)&E[r * EST + scol];
            float2 fa = __half22float2(reinterpret_cast<__half2&>(u.x));
            float2 fb = __half22float2(reinterpret_cast<__half2&>(u.y));
            float izr = iz[r];
            hs0 += fa.x * izr; hs1 += fa.y * izr;
            hs2 += fb.x * izr; hs3 += fb.y * izr;
        }
        atomicAdd(&hout[scol],     hs0);
        atomicAdd(&hout[scol + 1], hs1);
        atomicAdd(&hout[scol + 2], hs2);
        atomicAdd(&hout[scol + 3], hs3);
    }

    // ---- dist ----
    float dacc = 0.f;
    #pragma unroll
    for (int r = 0; r < 4; r++) {
        int id = tid + 256 * r;            // 0..1023
        int row = id >> 5, d = id & 31;
        float o = out_sf[row*33 + d] * iz[row];
        float qv = Qg[(size_t)(lbase + row) * CCH + h * DH + d];
        float e = qv - o;
        dacc += e * e;
    }
    #pragma unroll
    for (int o = 16; o; o >>= 1) dacc += __shfl_xor_sync(0xffffffffu, dacc, o);
    if (lane == 0) red[w] = dacc;
    __syncthreads();
    if (w == 0) {
        float v = (lane < 8) ? red[lane] : 0.f;
        #pragma unroll
        for (int o = 4; o; o >>= 1) v += __shfl_xor_sync(0xffffffffu, v, o);
        if (lane == 0) atomicAdd(&g_dist[gbp], v);
    }
}

// ---------------------------------------------------------------------------
// Finalize v2: 256 threads, one float4/thread, shuffle argmax.
// Tie rule matches jnp.argmax (first max): v> or (v== && idx<) wins.
__global__ void __launch_bounds__(256) finalize_kernel(float* __restrict__ out,
                                                       int out_size) {
    __shared__ float bvs[8];
    __shared__ int   bis[8];
    int gbp = blockIdx.x;
    int tid = threadIdx.x, lane = tid & 31, w = tid >> 5;
    const float* hrow = g_heat + (size_t)gbp * SSQ;

    float4 hv = *(const float4*)&hrow[tid * 4];
    float best = hv.x; int bi = tid * 4;
    if (hv.y > best) { best = hv.y; bi = tid*4 + 1; }
    if (hv.z > best) { best = hv.z; bi = tid*4 + 2; }
    if (hv.w > best) { best = hv.w; bi = tid*4 + 3; }

    #pragma unroll
    for (int o = 16; o; o >>= 1) {
        float v2 = __shfl_xor_sync(0xffffffffu, best, o);
        int   i2 = __shfl_xor_sync(0xffffffffu, bi, o);
        if (v2 > best || (v2 == best && i2 < bi)) { best = v2; bi = i2; }
    }
    if (lane == 0) { bvs[w] = best; bis[w] = bi; }
    __syncthreads();
    if (tid == 0) {
        best = bvs[0]; bi = bis[0];
        #pragma unroll
        for (int i = 1; i < 8; i++)
            if (bvs[i] > best || (bvs[i] == best && bis[i] < bi)) {
                best = bvs[i]; bi = bis[i];
            }
        int g = gbp >> 6, b = (gbp >> 3) & 7, p = gbp & 7;
        int col = g * PP + p;
        out[b * 24 + col] = g_dist[gbp] * (1.f / (64.f * 128.f));
        if (out_size >= 384)
            out[192 + b * 24 + col] = (float)bi;
    }
}

// ---------------------------------------------------------------------------
extern "C" void kernel_launch(void* const* d_in, const int* in_sizes, int n_in,
                              void* d_out, int out_size) {
    const float* x     = (const float*)d_in[0];
    const float* proto = (const float*)d_in[1];
    const float* qw    = (const float*)d_in[2];
    const float* kw    = (const float*)d_in[3];
    const float* vw    = (const float*)d_in[4];
    float* out = (float*)d_out;

    cudaFuncSetAttribute(attn_kernel,
                         cudaFuncAttributeMaxDynamicSharedMemorySize, AT_TOT);
    cudaFuncSetAttribute(proj_kv_mma_kernel,
                         cudaFuncAttributeMaxDynamicSharedMemorySize, PJ_TOT);
    cudaFuncSetAttribute(fused_pre_kernel,
                         cudaFuncAttributeMaxDynamicSharedMemorySize, FP_TOT);

    fused_pre_kernel<<<1120, 256, FP_TOT>>>(x, proto, qw, kw, vw);
    proj_kv_mma_kernel<<<dim3(8, 2, 24), 256, PJ_TOT>>>();
    attn_kernel<<<1536, 256, AT_TOT>>>();
    finalize_kernel<<<192, 256>>>(out, out_size);
}